// round 2
// baseline (speedup 1.0000x reference)
#include <cuda_runtime.h>
#include <cstdint>

#define N_VERTS 262144
#define N_PAIRS 8388608
#define DHAT2 0.0025f
#define EPSF 1e-12f

// Verts cached in shared memory per CTA (224 KB of float2).
#define CACHE_VERTS 28672
#define MAIN_BLOCK 1024
#define MAIN_GRID 148

// Scratch: current coordinates (rest + displacement), fits in L2 (2 MB).
__device__ float2 g_coords[N_VERTS];

// ---------------------------------------------------------------------------
// Kernel A: coords = rest + Uu.reshape(-1,2); also zero the output scalar.
// ---------------------------------------------------------------------------
__global__ void build_coords_kernel(const float* __restrict__ Uu,
                                    const float* __restrict__ rest,
                                    float* __restrict__ out) {
    int i = blockIdx.x * blockDim.x + threadIdx.x;
    if (i < N_VERTS) {
        float2 r = reinterpret_cast<const float2*>(rest)[i];
        float2 u = reinterpret_cast<const float2*>(Uu)[i];
        g_coords[i] = make_float2(r.x + u.x, r.y + u.y);
    }
    if (blockIdx.x == 0 && threadIdx.x == 0) {
        out[0] = 0.0f;  // d_out is poisoned; initialize
    }
}

// ---------------------------------------------------------------------------
// Predicated dual-path gather: smem if idx < CACHE_VERTS, else global (L1/L2).
// Inline PTX guarantees predication (no BSSY/BSYNC divergence).
// ---------------------------------------------------------------------------
__device__ __forceinline__ float2 gather_coord(uint32_t smem_base, int idx) {
    float2 r;
    asm("{\n\t"
        ".reg .pred p;\n\t"
        ".reg .u32 sa;\n\t"
        ".reg .u64 ga, gb;\n\t"
        "setp.lt.s32 p, %2, %4;\n\t"
        "mad.lo.u32 sa, %2, 8, %3;\n\t"
        "mov.u64 gb, g_coords;\n\t"
        "mul.wide.s32 ga, %2, 8;\n\t"
        "add.u64 ga, ga, gb;\n\t"
        "cvta.global.u64 ga, ga;\n\t"
        "@p  ld.shared.v2.f32 {%0,%1}, [sa];\n\t"
        "@!p ld.global.nc.v2.f32 {%0,%1}, [ga];\n\t"
        "}"
        : "=f"(r.x), "=f"(r.y)
        : "r"(idx), "r"(smem_base), "n"(CACHE_VERTS));
    return r;
}

// ---------------------------------------------------------------------------
// Per-pair barrier term (exact reference math, fp32).
// ---------------------------------------------------------------------------
__device__ __forceinline__ float pair_barrier(uint32_t sb, int iv, int ie0, int ie1) {
    float2 p = gather_coord(sb, iv);
    float2 a = gather_coord(sb, ie0);
    float2 b = gather_coord(sb, ie1);

    float abx = b.x - a.x, aby = b.y - a.y;
    float apx = p.x - a.x, apy = p.y - a.y;
    float denom = abx * abx + aby * aby;
    float t = (apx * abx + apy * aby) / fmaxf(denom, EPSF);
    t = fminf(fmaxf(t, 0.0f), 1.0f);
    float dx = apx - t * abx;
    float dy = apy - t * aby;
    float d2 = dx * dx + dy * dy;

    if (d2 < DHAT2) {
        float d2s = fmaxf(d2, EPSF);
        float m = d2s - DHAT2;
        return -(m * m) * logf(d2s / DHAT2);
    }
    return 0.0f;
}

// ---------------------------------------------------------------------------
// Kernel B: persistent CTAs; cache 28672 verts in smem; grid-stride over
// int4 pair groups; predicated smem/global gathers; block-reduce + atomic.
// ---------------------------------------------------------------------------
__global__ void __launch_bounds__(MAIN_BLOCK, 1)
barrier_energy_kernel(const int4* __restrict__ pv4,
                      const int4* __restrict__ pe04,
                      const int4* __restrict__ pe14,
                      float* __restrict__ out) {
    extern __shared__ float2 s_coords[];

    // Fill the smem vertex cache (coalesced from L2-resident g_coords).
    for (int i = threadIdx.x; i < CACHE_VERTS; i += MAIN_BLOCK)
        s_coords[i] = g_coords[i];
    __syncthreads();

    uint32_t sb;
    asm("{ .reg .u64 t; cvta.to.shared.u64 t, %1; cvt.u32.u64 %0, t; }"
        : "=r"(sb) : "l"(s_coords));

    const int n4 = N_PAIRS / 4;
    double acc = 0.0;

    for (int idx = blockIdx.x * MAIN_BLOCK + threadIdx.x; idx < n4;
         idx += MAIN_GRID * MAIN_BLOCK) {
        int4 v  = __ldg(&pv4[idx]);
        int4 e0 = __ldg(&pe04[idx]);
        int4 e1 = __ldg(&pe14[idx]);

        float s = pair_barrier(sb, v.x, e0.x, e1.x)
                + pair_barrier(sb, v.y, e0.y, e1.y)
                + pair_barrier(sb, v.z, e0.z, e1.z)
                + pair_barrier(sb, v.w, e0.w, e1.w);
        acc += (double)s;
    }

    // Warp reduction
    #pragma unroll
    for (int off = 16; off > 0; off >>= 1)
        acc += __shfl_xor_sync(0xFFFFFFFFu, acc, off);

    __shared__ double warp_sums[MAIN_BLOCK / 32];
    int lane = threadIdx.x & 31;
    int wid = threadIdx.x >> 5;
    if (lane == 0) warp_sums[wid] = acc;
    __syncthreads();

    if (wid == 0) {
        double vsum = (lane < (MAIN_BLOCK / 32)) ? warp_sums[lane] : 0.0;
        #pragma unroll
        for (int off = 16; off > 0; off >>= 1)
            vsum += __shfl_xor_sync(0xFFFFFFFFu, vsum, off);
        if (lane == 0)
            atomicAdd(out, (float)vsum);
    }
}

// ---------------------------------------------------------------------------
extern "C" void kernel_launch(void* const* d_in, const int* in_sizes, int n_in,
                              void* d_out, int out_size) {
    const float* Uu   = (const float*)d_in[0];
    const float* rest = (const float*)d_in[1];
    const int4* pv  = (const int4*)d_in[2];
    const int4* pe0 = (const int4*)d_in[3];
    const int4* pe1 = (const int4*)d_in[4];
    float* out = (float*)d_out;

    static bool attr_set = false;
    if (!attr_set) {
        cudaFuncSetAttribute(barrier_energy_kernel,
                             cudaFuncAttributeMaxDynamicSharedMemorySize,
                             CACHE_VERTS * sizeof(float2));
        attr_set = true;
    }

    build_coords_kernel<<<(N_VERTS + 255) / 256, 256>>>(Uu, rest, out);
    barrier_energy_kernel<<<MAIN_GRID, MAIN_BLOCK,
                            CACHE_VERTS * sizeof(float2)>>>(pv, pe0, pe1, out);
}